// round 14
// baseline (speedup 1.0000x reference)
#include <cuda_runtime.h>
#include <cstdint>

#define NB 8192      // batch
#define NA 128       // attr dim
#define NH 256       // hidden
#define NV 64        // vocab
#define NL 20        // rollout length
#define NBR 56       // batch rows per block (logical)
#define NBLK 147     // ceil(NB/NBR)
#define NT 512       // threads per block
#define HP 68        // padded b-stride (floats); groups at 16-float offsets -> 16B-aligned LDS.128

// logical row b -> physical smem column: group g=b/14 at g*16, offset b%14
#define PHYS(b) (((b) / 14) * 16 + ((b) % 14))

// ---- shared memory layout (float offsets) ----
#define OFF_HA   0
#define OFF_HB   (NH*HP)               // 17408
#define OFF_LG   (2*NH*HP)             // 34816: logits 56 x 64 (logical rows)
#define OFF_CH   (OFF_LG + NBR*64)     // 38400 (int[56])
#define OFF_SLP  (OFF_CH + 56)
#define OFF_PLP  (OFF_SLP + 56)
#define OFF_EP   (OFF_PLP + 56)
#define SMEM_FLOATS (OFF_EP + 56)      // 38624 floats = 154,496 B

// ---- reordered weight scratch ----
// W_hh duplicated: [p 2][k 256][nl 128][g 4][dup 2] float = 2 MB; +4096 floats pad
__device__ __align__(16) float  g_WhhD[2*256*1024 + 4096];
__device__ __align__(16) float4 g_WihR4[64*256];     // [ch][hh] -> 4 gates
__device__ __align__(16) float  g_WaR[128*256];      // [k][hh]
__device__ __align__(16) float4 g_biasR4[256];       // [hh] -> 4 gates (b_ih+b_hh)
__device__ __align__(16) float  g_WvD[256*64*2];     // [k][v][dup 2] duplicated W_v^T

struct Keys { unsigned int a[NL]; unsigned int b[NL]; };

typedef unsigned long long ull;

// ---------------- packed f32x2 helpers ----------------
__device__ __forceinline__ void ffma2(ull &d, ull a, ull b) {
    asm("fma.rn.f32x2 %0, %1, %2, %3;" : "=l"(d) : "l"(a), "l"(b), "l"(d));
}
__device__ __forceinline__ ull pack2(float lo, float hi) {
    ull r; asm("mov.b64 %0, {%1, %2};" : "=l"(r) : "f"(lo), "f"(hi)); return r;
}
__device__ __forceinline__ void unpack2(ull v, float &lo, float &hi) {
    asm("mov.b64 {%0, %1}, %2;" : "=f"(lo), "=f"(hi) : "l"(v));
}
// vector loads producing ready-packed 64-bit operands (no MOVs)
__device__ __forceinline__ void ldg_v2u64(ull &a, ull &b, const ull* p) {
    asm("ld.global.nc.v2.u64 {%0,%1}, [%2];" : "=l"(a), "=l"(b) : "l"(p));
}
__device__ __forceinline__ ull ldg_u64(const ull* p) {
    ull a; asm("ld.global.nc.u64 %0, [%1];" : "=l"(a) : "l"(p)); return a;
}
__device__ __forceinline__ void lds_v2u64(ull &a, ull &b, unsigned addr) {
    asm("ld.shared.v2.u64 {%0,%1}, [%2];" : "=l"(a), "=l"(b) : "r"(addr));
}
__device__ __forceinline__ void lds_u64(ull &a, unsigned addr) {
    asm("ld.shared.u64 %0, [%1];" : "=l"(a) : "r"(addr));
}

// ---------------- Threefry-2x32 (20 rounds), matches JAX ----------------
__host__ __device__ __forceinline__ uint32_t rotl32(uint32_t x, int r) {
    return (x << r) | (x >> (32 - r));
}
__host__ __device__ __forceinline__ void threefry2x32(
    uint32_t k0, uint32_t k1, uint32_t x0, uint32_t x1,
    uint32_t& o0, uint32_t& o1)
{
    uint32_t ks0 = k0, ks1 = k1, ks2 = k0 ^ k1 ^ 0x1BD11BDAu;
    x0 += ks0; x1 += ks1;
#define TF_RND(r) { x0 += x1; x1 = rotl32(x1, (r)); x1 ^= x0; }
    TF_RND(13) TF_RND(15) TF_RND(26) TF_RND(6)
    x0 += ks1; x1 += ks2 + 1u;
    TF_RND(17) TF_RND(29) TF_RND(16) TF_RND(24)
    x0 += ks2; x1 += ks0 + 2u;
    TF_RND(13) TF_RND(15) TF_RND(26) TF_RND(6)
    x0 += ks0; x1 += ks1 + 3u;
    TF_RND(17) TF_RND(29) TF_RND(16) TF_RND(24)
    x0 += ks1; x1 += ks2 + 4u;
    TF_RND(13) TF_RND(15) TF_RND(26) TF_RND(6)
    x0 += ks2; x1 += ks0 + 5u;
#undef TF_RND
    o0 = x0; o1 = x1;
}

__device__ __forceinline__ float sigf(float x) { return 1.0f / (1.0f + expf(-x)); }

// gumbel from raw bits — identical formula to rounds 1-12
__device__ __forceinline__ float gumbel_from(uint32_t sk0, uint32_t sk1, uint32_t ctr) {
    uint32_t o0, o1;
    threefry2x32(sk0, sk1, 0u, ctr, o0, o1);
    uint32_t bits = o0 ^ o1;
    float f = __uint_as_float((bits >> 9) | 0x3f800000u) - 1.0f;
    const float TINY = 1.17549435e-38f;
    float u = fmaxf(TINY, f * (1.0f - TINY) + TINY);
    return -logf(-logf(u));
}

// ---------------- prep: reorder weights ----------------
__global__ void prep_kernel(const float* __restrict__ Whh, const float* __restrict__ Wih,
                            const float* __restrict__ Wa,  const float* __restrict__ bih,
                            const float* __restrict__ bhh, const float* __restrict__ Wv)
{
    int idx = blockIdx.x * blockDim.x + threadIdx.x;
    if (idx < 2*256*1024) {
        // idx = (((p*256 + k)*128 + nl)*4 + g)*2 + dup
        int g = (idx >> 1) & 3, nl = (idx >> 3) & 127, k = (idx >> 10) & 255, p = idx >> 18;
        g_WhhD[idx] = Whh[(size_t)(g*256 + p*128 + nl) * 256 + k];
    }
    if (idx >= 2*256*1024 && idx < 2*256*1024 + 4096)
        g_WhhD[idx] = 0.0f;   // prefetch-overrun pad
    if (idx < 64*256*4) {
        int ch = idx >> 10, hh = (idx >> 2) & 255, g = idx & 3;
        ((float*)g_WihR4)[idx] = Wih[(size_t)(g*256 + hh) * 64 + ch];
    }
    if (idx < 128*256) {
        int k = idx >> 8, hh = idx & 255;
        g_WaR[idx] = Wa[(size_t)hh * 128 + k];
    }
    if (idx < 256*64*2) {
        int dup = idx & 1, v = (idx >> 1) & 63, k = idx >> 7;
        (void)dup;
        g_WvD[idx] = Wv[(size_t)v * NH + k];
    }
    if (idx < 1024) {
        int hh = idx >> 2, g = idx & 3;
        int gn = g*256 + hh;
        ((float*)g_biasR4)[idx] = bih[gn] + bhh[gn];
    }
}

// ---------------- GEMM pass: duplicated-W LDG + vector LDS, zero pack MOVs ----------------
// Per kk per warp: 2x LDG.128 (W, 4 packed gate weights) + 3x LDS.128 + 1 LDS.64 (7 h pairs)
// + 28 ffma2 = 34 issues. No barriers, no MOVs.
__device__ __forceinline__ void gemm_pass(ull (&acc)[7][4], unsigned hb, int p, int nl)
{
    // W base in ull units: (((p*256 + k)*128 + nl)*4 + g)*2 floats = k*512 ull + nl*4 ull
    const ull* Wp = (const ull*)g_WhhD + ((size_t)p * 256 * 512 + (size_t)nl * 4);
    // prefetch ring, distance 4 kk
    ull wA[4][2], wB[4][2];
#pragma unroll
    for (int j = 0; j < 4; j++) {
        ldg_v2u64(wA[j][0], wA[j][1], Wp + (size_t)j * 512);
        ldg_v2u64(wB[j][0], wB[j][1], Wp + (size_t)j * 512 + 2);
    }
#pragma unroll 1
    for (int kt = 0; kt < 256; kt += 4) {
#pragma unroll
        for (int j = 0; j < 4; j++) {
            int kk = kt + j;
            ull W0 = wA[j][0], W1 = wA[j][1], W2 = wB[j][0], W3 = wB[j][1];
            ldg_v2u64(wA[j][0], wA[j][1], Wp + (size_t)(kk + 4) * 512);      // pad covers overrun
            ldg_v2u64(wB[j][0], wB[j][1], Wp + (size_t)(kk + 4) * 512 + 2);
            unsigned ha = hb + (unsigned)kk * (HP * 4);
            ull hp0, hp1, hp2, hp3, hp4, hp5, hp6;
            lds_v2u64(hp0, hp1, ha);
            lds_v2u64(hp2, hp3, ha + 16);
            lds_v2u64(hp4, hp5, ha + 32);
            lds_u64(hp6, ha + 48);
            ffma2(acc[0][0], hp0, W0); ffma2(acc[0][1], hp0, W1);
            ffma2(acc[0][2], hp0, W2); ffma2(acc[0][3], hp0, W3);
            ffma2(acc[1][0], hp1, W0); ffma2(acc[1][1], hp1, W1);
            ffma2(acc[1][2], hp1, W2); ffma2(acc[1][3], hp1, W3);
            ffma2(acc[2][0], hp2, W0); ffma2(acc[2][1], hp2, W1);
            ffma2(acc[2][2], hp2, W2); ffma2(acc[2][3], hp2, W3);
            ffma2(acc[3][0], hp3, W0); ffma2(acc[3][1], hp3, W1);
            ffma2(acc[3][2], hp3, W2); ffma2(acc[3][3], hp3, W3);
            ffma2(acc[4][0], hp4, W0); ffma2(acc[4][1], hp4, W1);
            ffma2(acc[4][2], hp4, W2); ffma2(acc[4][3], hp4, W3);
            ffma2(acc[5][0], hp5, W0); ffma2(acc[5][1], hp5, W1);
            ffma2(acc[5][2], hp5, W2); ffma2(acc[5][3], hp5, W3);
            ffma2(acc[6][0], hp6, W0); ffma2(acc[6][1], hp6, W1);
            ffma2(acc[6][2], hp6, W2); ffma2(acc[6][3], hp6, W3);
        }
    }
}

__device__ __forceinline__ void zero_acc(ull (&acc)[7][4]) {
#pragma unroll
    for (int i = 0; i < 7; i++)
#pragma unroll
        for (int g = 0; g < 4; g++) acc[i][g] = 0ull;
}

// ---------------- LSTM epilogue for one pass (bit-identical math) ----------------
template<bool hasX>
__device__ __forceinline__ void lstm_epilogue(float* sm, float* hnew, float* cc,
                                              ull (&acc)[7][4], int p, int nl,
                                              int b0L, int b0P)
{
    const int hh = p * 128 + nl;
    float4 bb = g_biasR4[hh];
    const int* s_ch = (const int*)sm + OFF_CH;
#pragma unroll
    for (int i = 0; i < 7; i++) {
        float a0[4], a1[4];
#pragma unroll
        for (int g = 0; g < 4; g++) unpack2(acc[i][g], a0[g], a1[g]);
        float hn[2];
#pragma unroll
        for (int ro = 0; ro < 2; ro++) {
            float* ar = ro ? a1 : a0;
            int b = b0L + 2 * i + ro;   // logical row for ch lookup
            float xx = 0.f, xy = 0.f, xz = 0.f, xw = 0.f;
            if (hasX) {
                int ch = s_ch[b];
                float4 xg = g_WihR4[ch * 256 + hh];
                xx = xg.x; xy = xg.y; xz = xg.z; xw = xg.w;
            }
            float gi = ar[0] + bb.x + xx;
            float gf = ar[1] + bb.y + xy;
            float gg = ar[2] + bb.z + xz;
            float go = ar[3] + bb.w + xw;
            float cv = cc[p * 14 + 2 * i + ro];
            float cn = sigf(gf) * cv + sigf(gi) * tanhf(gg);
            cc[p * 14 + 2 * i + ro] = cn;
            hn[ro] = sigf(go) * tanhf(cn);
        }
        *(ull*)(hnew + hh * HP + b0P + 2 * i) = pack2(hn[0], hn[1]);
    }
}

// ---------------- one LSTM step ----------------
template<bool hasX>
__device__ __forceinline__ void lstm_step(float* sm, const float* hcur, float* hnew,
                                          float* cc, int nl, int b0L, int b0P)
{
    unsigned hb = (unsigned)__cvta_generic_to_shared(hcur + b0P);
#pragma unroll
    for (int p = 0; p < 2; p++) {
        ull acc[7][4];
        zero_acc(acc);
        gemm_pass(acc, hb, p, nl);
        lstm_epilogue<hasX>(sm, hnew, cc, acc, p, nl, b0L, b0P);
    }
    __syncthreads();
}

// ---------------- per-row reduction + gumbel sample (bit-identical to R4-R12) ----------------
__device__ __forceinline__ void reduce_row(float* sm, int r, int base, int lane,
        float* __restrict__ out, int t, uint32_t sk0, uint32_t sk1)
{
    int* si = (int*)sm;
    int gb = base + r;
    float la0 = sm[OFF_LG + r * 64 + 2 * lane];
    float la1 = sm[OFF_LG + r * 64 + 2 * lane + 1];
    float m = fmaxf(la0, la1);
#pragma unroll
    for (int o = 16; o; o >>= 1) m = fmaxf(m, __shfl_xor_sync(0xffffffffu, m, o));
    float S = expf(la0 - m) + expf(la1 - m);
#pragma unroll
    for (int o = 16; o; o >>= 1) S += __shfl_xor_sync(0xffffffffu, S, o);
    float lse = logf(S);
    float lp0 = (la0 - m) - lse;
    float lp1 = (la1 - m) - lse;
    float pt = expf(lp0) * lp0 + expf(lp1) * lp1;
#pragma unroll
    for (int o = 16; o; o >>= 1) pt += __shfl_xor_sync(0xffffffffu, pt, o);
    float g0 = gumbel_from(sk0, sk1, (uint32_t)(gb * NV + 2 * lane));
    float g1 = gumbel_from(sk0, sk1, (uint32_t)(gb * NV + 2 * lane + 1));
    float z0 = la0 + g0, z1 = la1 + g1;
    float z; int idx;
    if (z1 > z0) { z = z1; idx = 2 * lane + 1; }
    else         { z = z0; idx = 2 * lane; }
#pragma unroll
    for (int o = 16; o; o >>= 1) {
        float oz = __shfl_xor_sync(0xffffffffu, z, o);
        int   oi = __shfl_xor_sync(0xffffffffu, idx, o);
        if (oz > z || (oz == z && oi < idx)) { z = oz; idx = oi; }
    }
    float lpA = __shfl_sync(0xffffffffu, lp0, idx >> 1);
    float lpB = __shfl_sync(0xffffffffu, lp1, idx >> 1);
    float lp = (idx & 1) ? lpB : lpA;
    if (lane == 0) {
        si[OFF_CH + r] = idx;
        sm[OFF_SLP + r] += lp;
        sm[OFF_PLP + r] += pt;
        sm[OFF_EP + r] *= expf(lp);
        if (gb < NB) out[(size_t)gb * NL + t] = (float)idx;   // bounds guard
    }
}

// ---------------- sampling: logits (bit-exact) + row-parallel reductions ----------------
__device__ __forceinline__ void sample_step(float* sm, const float* hcur,
        const float* __restrict__ bv, float* __restrict__ out, int t, int base,
        int tid, uint32_t sk0, uint32_t sk1)
{
    const int sbg = tid >> 6;          // 8 groups of 7 logical rows
    const int v = tid & 63;
    const int b0s = sbg * 7;                                   // logical
    const int pb0 = (sbg >> 1) * 16 + (sbg & 1) * 7;           // physical
    const int p0 = (sbg & 1) ? 1 : 0;  // aligned pair base
    const int sc = (sbg & 1) ? 0 : 6;  // leftover scalar row
    float bvv = bv[v];
    ull accp[3];
    accp[0] = pack2(bvv, bvv); accp[1] = accp[0]; accp[2] = accp[0];
    float accs = bvv;
    const float* hs = hcur + pb0;
    const ull* wvk = (const ull*)g_WvD + v;
#pragma unroll 4
    for (int kk = 0; kk < NH; kk++) {
        ull w2 = ldg_u64(wvk + (size_t)kk * 64);   // (w,w) pre-duplicated
        float w; { float whi; unpack2(w2, w, whi); (void)whi; }
        ffma2(accp[0], *(const ull*)(hs + kk * HP + p0), w2);
        ffma2(accp[1], *(const ull*)(hs + kk * HP + p0 + 2), w2);
        ffma2(accp[2], *(const ull*)(hs + kk * HP + p0 + 4), w2);
        accs = fmaf(hs[kk * HP + sc], w, accs);
    }
#pragma unroll
    for (int j = 0; j < 3; j++) {
        float lo, hi; unpack2(accp[j], lo, hi);
        sm[OFF_LG + (b0s + p0 + 2*j    ) * 64 + v] = lo;
        sm[OFF_LG + (b0s + p0 + 2*j + 1) * 64 + v] = hi;
    }
    sm[OFF_LG + (b0s + sc) * 64 + v] = accs;
    __syncthreads();

    const int warp = tid >> 5, lane = tid & 31;
    for (int r = warp; r < NBR; r += 16)
        reduce_row(sm, r, base, lane, out, t, sk0, sk1);
    __syncthreads();
}

// ---------------- fused persistent rollout kernel ----------------
__global__ __launch_bounds__(NT, 1) void sender_kernel(
    const float* __restrict__ attr, const float* __restrict__ bv,
    const float* __restrict__ ba, float* __restrict__ out, Keys keys)
{
    extern __shared__ float sm[];
    const int tid = threadIdx.x;
    const int bq = tid >> 7;        // 4 groups
    const int nl = tid & 127;       // 128 n-columns
    const int b0L = bq * 14;        // logical row base
    const int b0P = bq * 16;        // physical row base (16-float aligned)
    const int base = blockIdx.x * NBR;

    float cc[28];
#pragma unroll
    for (int i = 0; i < 28; i++) cc[i] = 0.0f;

    if (tid < NBR) { sm[OFF_SLP + tid] = 0.0f; sm[OFF_PLP + tid] = 0.0f; sm[OFF_EP + tid] = 1.0f; }

    // stage attr tile [k 128][physical b] stride HP into hB region
    for (int idx = tid; idx < NBR * 32; idx += NT) {
        int b = idx >> 5, f4 = idx & 31;
        int gb = base + b;
        int pb = PHYS(b);
        float4 a = make_float4(0.f, 0.f, 0.f, 0.f);
        if (gb < NB) a = ((const float4*)attr)[(size_t)gb * 32 + f4];
        sm[OFF_HB + (f4*4+0)*HP + pb] = a.x;
        sm[OFF_HB + (f4*4+1)*HP + pb] = a.y;
        sm[OFF_HB + (f4*4+2)*HP + pb] = a.z;
        sm[OFF_HB + (f4*4+3)*HP + pb] = a.w;
    }
    __syncthreads();

    // h0 = attr @ W_a^T + b_a  (identical arithmetic to R2-R12)
#pragma unroll
    for (int p = 0; p < 2; p++) {
        const int hh = p * 128 + nl;
        ull acc0[7];
#pragma unroll
        for (int i = 0; i < 7; i++) acc0[i] = 0ull;
        const float* wr = g_WaR + hh;
        const float* ak = sm + OFF_HB + b0P;
#pragma unroll 4
        for (int k = 0; k < NA; k++) {
            float w = wr[k * 256];
            ull w2 = pack2(w, w);
#pragma unroll
            for (int i = 0; i < 7; i++) {
                ull h2 = *(const ull*)(ak + k * HP + 2 * i);
                ffma2(acc0[i], h2, w2);
            }
        }
        float bbv = ba[hh];
#pragma unroll
        for (int i = 0; i < 7; i++) {
            float lo, hi; unpack2(acc0[i], lo, hi);
            *(ull*)(sm + OFF_HA + hh * HP + b0P + 2 * i) = pack2(lo + bbv, hi + bbv);
        }
    }
    __syncthreads();

    float* hA = sm + OFF_HA;
    float* hB = sm + OFF_HB;

    // start-token step (x = 0): hA -> hB
    lstm_step<false>(sm, hA, hB, cc, nl, b0L, b0P);

    float* hc = hB;
    float* hn = hA;
    for (int t = 0; t < NL; t++) {
        sample_step(sm, hc, bv, out, t, base, tid, keys.a[t], keys.b[t]);
        if (t < NL - 1) {
            lstm_step<true>(sm, hc, hn, cc, nl, b0L, b0P);
            float* tmp = hc; hc = hn; hn = tmp;
        }
    }

    for (int i = tid; i < NBR; i += NT) {
        int gb = base + i;
        if (gb < NB) {
            out[NB*NL + gb]        = sm[OFF_SLP + i];
            out[NB*NL + NB + gb]   = sm[OFF_PLP + i];
            out[NB*NL + 2*NB + gb] = sm[OFF_EP + i];
        }
    }
}

// ---------------- launcher ----------------
extern "C" void kernel_launch(void* const* d_in, const int* in_sizes, int n_in,
                              void* d_out, int out_size)
{
    const float* attr = (const float*)d_in[0];
    const float* W_a  = (const float*)d_in[1];
    const float* b_a  = (const float*)d_in[2];
    const float* W_ih = (const float*)d_in[3];
    const float* W_hh = (const float*)d_in[4];
    const float* b_ih = (const float*)d_in[5];
    const float* b_hh = (const float*)d_in[6];
    const float* W_v  = (const float*)d_in[7];
    const float* b_v  = (const float*)d_in[8];
    float* out = (float*)d_out;

    Keys keys;
    for (int t = 0; t < NL; t++) {
        uint32_t s0, s1;
        threefry2x32(0u, 42u, 0u, (uint32_t)t, s0, s1);
        keys.a[t] = s0; keys.b[t] = s1;
    }

    static int smem_set = 0;
    if (!smem_set) {
        cudaFuncSetAttribute(sender_kernel, cudaFuncAttributeMaxDynamicSharedMemorySize,
                             SMEM_FLOATS * sizeof(float));
        smem_set = 1;
    }

    prep_kernel<<<2080, 256>>>(W_hh, W_ih, W_a, b_ih, b_hh, W_v);
    sender_kernel<<<NBLK, NT, SMEM_FLOATS * sizeof(float)>>>(attr, b_v, b_a, out, keys);
}

// round 15
// speedup vs baseline: 1.2927x; 1.2927x over previous
#include <cuda_runtime.h>
#include <cstdint>

#define NB 8192      // batch
#define NA 128       // attr dim
#define NH 256       // hidden
#define NV 64        // vocab
#define NL 20        // rollout length
#define NBR 56       // batch rows per block
#define NBLK 147     // ceil(NB/NBR)
#define NT 512       // threads per block
#define HP 58        // padded b-stride for h smem (even for f32x2)
#define WTS 516      // W tile row stride (floats)
#define BUFF 8320    // floats per W tile buffer

// ---- shared memory layout (float offsets) ----
#define OFF_HA   0
#define OFF_HB   (NH*HP)               // 14848
#define OFF_WT   (2*NH*HP)             // 29696: 3 tile buffers
#define OFF_LG   (OFF_WT + 2*BUFF)     // logits 56 x 64 (aliases buf2 during sampling)
#define OFF_CH   (OFF_WT + 3*BUFF)     // int[56]
#define SMEM_FLOATS (OFF_CH + 56)      // 54712 floats = 218,848 B

// ---- reordered weight scratch ----
__device__ __align__(16) float  g_WhhR[2*256*512];   // [pass][k 256][n' = g*128+nl]
__device__ __align__(16) float4 g_WihR4[64*256];     // [ch][hh] -> 4 gates
__device__ __align__(16) float  g_WaR[128*256];      // [k][hh]
__device__ __align__(16) float4 g_biasR4[256];       // [hh] -> 4 gates (b_ih+b_hh)
// ---- big tables: precomputed gumbel noise + streamed logits ----
__device__ float g_gum[(size_t)NL*NB*NV];            // [t][b][v]
__device__ float g_logits[(size_t)NL*NB*NV];         // [t][b][v]

struct Keys { unsigned int a[NL]; unsigned int b[NL]; };

typedef unsigned long long ull;

// ---------------- packed f32x2 helpers ----------------
__device__ __forceinline__ void ffma2(ull &d, ull a, ull b) {
    asm("fma.rn.f32x2 %0, %1, %2, %3;" : "=l"(d) : "l"(a), "l"(b), "l"(d));
}
__device__ __forceinline__ ull pack2(float lo, float hi) {
    ull r; asm("mov.b64 %0, {%1, %2};" : "=l"(r) : "f"(lo), "f"(hi)); return r;
}
__device__ __forceinline__ void unpack2(ull v, float &lo, float &hi) {
    asm("mov.b64 {%0, %1}, %2;" : "=f"(lo), "=f"(hi) : "l"(v));
}

// ---------------- cp.async helpers ----------------
__device__ __forceinline__ void cp16(float* dst_smem, const float* src) {
    unsigned sdst = (unsigned)__cvta_generic_to_shared(dst_smem);
    asm volatile("cp.async.cg.shared.global [%0], [%1], 16;" :: "r"(sdst), "l"(src));
}
__device__ __forceinline__ void cp_commit() { asm volatile("cp.async.commit_group;"); }
__device__ __forceinline__ void cp_wait1() { asm volatile("cp.async.wait_group 1;"); }
__device__ __forceinline__ void cp_wait0() { asm volatile("cp.async.wait_group 0;"); }

// ---------------- Threefry-2x32 (20 rounds), matches JAX ----------------
__host__ __device__ __forceinline__ uint32_t rotl32(uint32_t x, int r) {
    return (x << r) | (x >> (32 - r));
}
__host__ __device__ __forceinline__ void threefry2x32(
    uint32_t k0, uint32_t k1, uint32_t x0, uint32_t x1,
    uint32_t& o0, uint32_t& o1)
{
    uint32_t ks0 = k0, ks1 = k1, ks2 = k0 ^ k1 ^ 0x1BD11BDAu;
    x0 += ks0; x1 += ks1;
#define TF_RND(r) { x0 += x1; x1 = rotl32(x1, (r)); x1 ^= x0; }
    TF_RND(13) TF_RND(15) TF_RND(26) TF_RND(6)
    x0 += ks1; x1 += ks2 + 1u;
    TF_RND(17) TF_RND(29) TF_RND(16) TF_RND(24)
    x0 += ks2; x1 += ks0 + 2u;
    TF_RND(13) TF_RND(15) TF_RND(26) TF_RND(6)
    x0 += ks0; x1 += ks1 + 3u;
    TF_RND(17) TF_RND(29) TF_RND(16) TF_RND(24)
    x0 += ks1; x1 += ks2 + 4u;
    TF_RND(13) TF_RND(15) TF_RND(26) TF_RND(6)
    x0 += ks2; x1 += ks0 + 5u;
#undef TF_RND
    o0 = x0; o1 = x1;
}

__device__ __forceinline__ float sigf(float x) { return 1.0f / (1.0f + expf(-x)); }

// gumbel from raw bits — identical formula to rounds 1-13
__device__ __forceinline__ float gumbel_from(uint32_t sk0, uint32_t sk1, uint32_t ctr) {
    uint32_t o0, o1;
    threefry2x32(sk0, sk1, 0u, ctr, o0, o1);
    uint32_t bits = o0 ^ o1;
    float f = __uint_as_float((bits >> 9) | 0x3f800000u) - 1.0f;
    const float TINY = 1.17549435e-38f;
    float u = fmaxf(TINY, f * (1.0f - TINY) + TINY);
    return -logf(-logf(u));
}

// ---------------- prep: reorder weights ----------------
__global__ void prep_kernel(const float* __restrict__ Whh, const float* __restrict__ Wih,
                            const float* __restrict__ Wa,  const float* __restrict__ bih,
                            const float* __restrict__ bhh)
{
    int idx = blockIdx.x * blockDim.x + threadIdx.x;
    if (idx < 2*256*512) {
        int p = idx >> 17, rem = idx & 131071, k = rem >> 9, n = rem & 511;
        int g = n >> 7, nl = n & 127;
        g_WhhR[idx] = Whh[(size_t)(g*256 + p*128 + nl) * 256 + k];
    }
    if (idx < 64*256*4) {
        int ch = idx >> 10, hh = (idx >> 2) & 255, g = idx & 3;
        ((float*)g_WihR4)[idx] = Wih[(size_t)(g*256 + hh) * 64 + ch];
    }
    if (idx < 128*256) {
        int k = idx >> 8, hh = idx & 255;
        g_WaR[idx] = Wa[(size_t)hh * 128 + k];
    }
    if (idx < 1024) {
        int hh = idx >> 2, g = idx & 3;
        int gn = g*256 + hh;
        ((float*)g_biasR4)[idx] = bih[gn] + bhh[gn];
    }
}

// ---------------- prep: gumbel noise table (exact counters as rounds 1-13) ----------------
__global__ void prep_gum(Keys keys) {
    int idx = blockIdx.x * blockDim.x + threadIdx.x;
    if (idx < NL * NB * NV) {
        int t = idx >> 19;              // NB*NV = 524288 = 2^19
        int rem = idx & 524287;
        // ctr = b*NV + v = rem exactly
        g_gum[idx] = gumbel_from(keys.a[t], keys.b[t], (uint32_t)rem);
    }
}

// ---------------- W tile async load: 16 k rows x 512 cols ----------------
__device__ __forceinline__ void issue_tile(float* buf, int kt, int tid) {
    const float* src = g_WhhR + (size_t)kt * 16 * 512;
#pragma unroll
    for (int s = 0; s < 4; s++) {
        int i = tid + s * NT;
        int kk = i >> 7, c4 = i & 127;
        cp16(buf + kk * WTS + c4 * 4, src + kk * 512 + c4 * 4);
    }
    cp_commit();
}

// ---------------- LSTM epilogue for one pass (bit-identical to R3-R13) ----------------
template<bool hasX>
__device__ __forceinline__ void lstm_epilogue(float* sm, float* hnew, float* cc,
                                              ull (&acc)[7][4], int p, int nl, int b0)
{
    const int hh = p * 128 + nl;
    float4 bb = g_biasR4[hh];
    const int* s_ch = (const int*)sm + OFF_CH;
#pragma unroll
    for (int i = 0; i < 7; i++) {
        float a0[4], a1[4];
#pragma unroll
        for (int g = 0; g < 4; g++) unpack2(acc[i][g], a0[g], a1[g]);
        float hn[2];
#pragma unroll
        for (int ro = 0; ro < 2; ro++) {
            float* ar = ro ? a1 : a0;
            int b = b0 + 2 * i + ro;
            float xx = 0.f, xy = 0.f, xz = 0.f, xw = 0.f;
            if (hasX) {
                int ch = s_ch[b];
                float4 xg = g_WihR4[ch * 256 + hh];
                xx = xg.x; xy = xg.y; xz = xg.z; xw = xg.w;
            }
            float gi = ar[0] + bb.x + xx;
            float gf = ar[1] + bb.y + xy;
            float gg = ar[2] + bb.z + xz;
            float go = ar[3] + bb.w + xw;
            float cv = cc[p * 14 + 2 * i + ro];
            float cn = sigf(gf) * cv + sigf(gi) * tanhf(gg);
            cc[p * 14 + 2 * i + ro] = cn;
            hn[ro] = sigf(go) * tanhf(cn);
        }
        *(ull*)(hnew + hh * HP + b0 + 2 * i) = pack2(hn[0], hn[1]);
    }
}

// ---------------- one LSTM step: triple-buffered GEMM (verbatim R4) ----------------
template<bool hasX>
__device__ __forceinline__ void lstm_step(float* sm, const float* hcur, float* hnew,
                                          float* cc, int tid, int nl, int b0)
{
    float* bA = sm + OFF_WT;
    float* bB = bA + BUFF;
    float* bC = bB + BUFF;

    issue_tile(bA, 0, tid);
    issue_tile(bB, 1, tid);

    ull acc[7][4];
#pragma unroll
    for (int i = 0; i < 7; i++)
#pragma unroll
        for (int g = 0; g < 4; g++) acc[i][g] = 0ull;

#pragma unroll 1
    for (int kt = 0; kt < 32; kt++) {
        if (kt < 31) cp_wait1(); else cp_wait0();
        __syncthreads();
        if (kt + 2 < 32) issue_tile(bC, kt + 2, tid);

        const float* wk = bA + nl;
        const float* hk = hcur + (kt & 15) * 16 * HP + b0;
#pragma unroll
        for (int kk = 0; kk < 16; kk++) {
            float w0 = wk[kk*WTS      ];
            float w1 = wk[kk*WTS + 128];
            float w2 = wk[kk*WTS + 256];
            float w3 = wk[kk*WTS + 384];
            ull W0 = pack2(w0, w0), W1 = pack2(w1, w1);
            ull W2 = pack2(w2, w2), W3 = pack2(w3, w3);
#pragma unroll
            for (int i = 0; i < 7; i++) {
                ull h2 = *(const ull*)(hk + kk * HP + 2 * i);
                ffma2(acc[i][0], h2, W0);
                ffma2(acc[i][1], h2, W1);
                ffma2(acc[i][2], h2, W2);
                ffma2(acc[i][3], h2, W3);
            }
        }

        if (kt == 15) {
            lstm_epilogue<hasX>(sm, hnew, cc, acc, 0, nl, b0);
#pragma unroll
            for (int i = 0; i < 7; i++)
#pragma unroll
                for (int g = 0; g < 4; g++) acc[i][g] = 0ull;
        }

        float* tmp = bA; bA = bB; bB = bC; bC = tmp;
    }
    lstm_epilogue<hasX>(sm, hnew, cc, acc, 1, nl, b0);
    __syncthreads();
}

// ---------------- lite per-row argmax (gumbel from table; no softmax work) ----------------
__device__ __forceinline__ void reduce_lite(float* sm, int r, int base, int lane,
                                            float* __restrict__ out, int t)
{
    int* si = (int*)sm;
    int gb = base + r;
    int gbc = gb < NB ? gb : NB - 1;     // clamp for table read validity only
    float la0 = sm[OFF_LG + r * 64 + 2 * lane];
    float la1 = sm[OFF_LG + r * 64 + 2 * lane + 1];
    ull gg = *(const ull*)(g_gum + ((size_t)t * NB + gbc) * 64 + 2 * lane);
    float g0, g1; unpack2(gg, g0, g1);
    float z0 = la0 + g0, z1 = la1 + g1;
    float z; int idx;
    if (z1 > z0) { z = z1; idx = 2 * lane + 1; }
    else         { z = z0; idx = 2 * lane; }
#pragma unroll
    for (int o = 16; o; o >>= 1) {
        float oz = __shfl_xor_sync(0xffffffffu, z, o);
        int   oi = __shfl_xor_sync(0xffffffffu, idx, o);
        if (oz > z || (oz == z && oi < idx)) { z = oz; idx = oi; }
    }
    if (lane == 0) {
        si[OFF_CH + r] = idx;
        if (gb < NB) out[(size_t)gb * NL + t] = (float)idx;
    }
}

// ---------------- sampling: logits (bit-exact R4 chain) + lite argmax ----------------
__device__ __forceinline__ void sample_step(float* sm, const float* hcur,
        const float* __restrict__ Wv, const float* __restrict__ bv,
        float* __restrict__ out, int t, int base, int tid)
{
    // stage W_v as [k 256][v 64] stride 65 (buffers 0-1)
    for (int idx = tid; idx < NV * NH; idx += NT) {
        int k = idx & 255, v = idx >> 8;
        sm[OFF_WT + k * 65 + v] = Wv[(size_t)v * NH + k];
    }
    __syncthreads();

    const int sbg = tid >> 6;          // 8 groups of 7 rows
    const int v = tid & 63;
    const int b0s = sbg * 7;
    const int p0 = (sbg & 1) ? 1 : 0;  // aligned pair base
    const int sc = (sbg & 1) ? 0 : 6;  // leftover scalar row
    float bvv = bv[v];
    ull accp[3];
    accp[0] = pack2(bvv, bvv); accp[1] = accp[0]; accp[2] = accp[0];
    float accs = bvv;
    const float* hs = hcur + b0s;
    const float* wk = sm + OFF_WT + v;
#pragma unroll 4
    for (int kk = 0; kk < NH; kk++) {
        float w = wk[kk * 65];
        ull w2 = pack2(w, w);
        ffma2(accp[0], *(const ull*)(hs + kk * HP + p0), w2);
        ffma2(accp[1], *(const ull*)(hs + kk * HP + p0 + 2), w2);
        ffma2(accp[2], *(const ull*)(hs + kk * HP + p0 + 4), w2);
        accs = fmaf(hs[kk * HP + sc], w, accs);
    }
    // write logits: smem (argmax) + gmem (postlude)
    float* lgm = g_logits + ((size_t)t * NB) * 64;
#pragma unroll
    for (int j = 0; j < 3; j++) {
        float lo, hi; unpack2(accp[j], lo, hi);
        int r0 = b0s + p0 + 2*j, r1 = r0 + 1;
        sm[OFF_LG + r0 * 64 + v] = lo;
        sm[OFF_LG + r1 * 64 + v] = hi;
        if (base + r0 < NB) lgm[(size_t)(base + r0) * 64 + v] = lo;
        if (base + r1 < NB) lgm[(size_t)(base + r1) * 64 + v] = hi;
    }
    sm[OFF_LG + (b0s + sc) * 64 + v] = accs;
    if (base + b0s + sc < NB) lgm[(size_t)(base + b0s + sc) * 64 + v] = accs;
    __syncthreads();

    const int warp = tid >> 5, lane = tid & 31;
    for (int r = warp; r < NBR; r += 16)
        reduce_lite(sm, r, base, lane, out, t);
    __syncthreads();
}

// ---------------- fused persistent rollout kernel ----------------
__global__ __launch_bounds__(NT, 1) void sender_kernel(
    const float* __restrict__ attr, const float* __restrict__ Wv,
    const float* __restrict__ bv,   const float* __restrict__ ba,
    float* __restrict__ out)
{
    extern __shared__ float sm[];
    const int tid = threadIdx.x;
    const int bq = tid >> 7;        // 4 groups
    const int nl = tid & 127;       // 128 n-columns
    const int b0 = bq * 14;         // 14 rows (7 f32x2 pairs)
    const int base = blockIdx.x * NBR;

    float cc[28];
#pragma unroll
    for (int i = 0; i < 28; i++) cc[i] = 0.0f;

    // stage attr tile [k 128][b] stride HP into tile-buffer area
    for (int idx = tid; idx < NBR * 32; idx += NT) {
        int b = idx >> 5, f4 = idx & 31;
        int gb = base + b;
        float4 a = make_float4(0.f, 0.f, 0.f, 0.f);
        if (gb < NB) a = ((const float4*)attr)[(size_t)gb * 32 + f4];
        sm[OFF_WT + (f4*4+0)*HP + b] = a.x;
        sm[OFF_WT + (f4*4+1)*HP + b] = a.y;
        sm[OFF_WT + (f4*4+2)*HP + b] = a.z;
        sm[OFF_WT + (f4*4+3)*HP + b] = a.w;
    }
    __syncthreads();

    // h0 = attr @ W_a^T + b_a  (identical arithmetic to R2-R13)
#pragma unroll
    for (int p = 0; p < 2; p++) {
        const int hh = p * 128 + nl;
        ull acc0[7];
#pragma unroll
        for (int i = 0; i < 7; i++) acc0[i] = 0ull;
        const float* wr = g_WaR + hh;
        const float* ak = sm + OFF_WT + b0;
#pragma unroll 4
        for (int k = 0; k < NA; k++) {
            float w = wr[k * 256];
            ull w2 = pack2(w, w);
#pragma unroll
            for (int i = 0; i < 7; i++) {
                ull h2 = *(const ull*)(ak + k * HP + 2 * i);
                ffma2(acc0[i], h2, w2);
            }
        }
        float bbv = ba[hh];
#pragma unroll
        for (int i = 0; i < 7; i++) {
            float lo, hi; unpack2(acc0[i], lo, hi);
            *(ull*)(sm + OFF_HA + hh * HP + b0 + 2 * i) = pack2(lo + bbv, hi + bbv);
        }
    }
    __syncthreads();

    float* hA = sm + OFF_HA;
    float* hB = sm + OFF_HB;

    // start-token step (x = 0): hA -> hB
    lstm_step<false>(sm, hA, hB, cc, tid, nl, b0);

    float* hc = hB;
    float* hn = hA;
    for (int t = 0; t < NL; t++) {
        sample_step(sm, hc, Wv, bv, out, t, base, tid);
        if (t < NL - 1) {
            lstm_step<true>(sm, hc, hn, cc, tid, nl, b0);
            float* tmp = hc; hc = hn; hn = tmp;
        }
    }
}

// ---------------- postlude: softmax stats (bit-identical R4 reduction order) ----------------
__global__ __launch_bounds__(256) void post_kernel(float* __restrict__ out)
{
    int gwarp = (blockIdx.x * blockDim.x + threadIdx.x) >> 5;
    int lane = threadIdx.x & 31;
    if (gwarp >= NB) return;
    int b = gwarp;
    float slp = 0.0f, plp = 0.0f, ep = 1.0f;
#pragma unroll 1
    for (int t = 0; t < NL; t++) {
        const float* lrow = g_logits + ((size_t)t * NB + b) * 64;
        float la0 = lrow[2 * lane];
        float la1 = lrow[2 * lane + 1];
        float m = fmaxf(la0, la1);
#pragma unroll
        for (int o = 16; o; o >>= 1) m = fmaxf(m, __shfl_xor_sync(0xffffffffu, m, o));
        float S = expf(la0 - m) + expf(la1 - m);
#pragma unroll
        for (int o = 16; o; o >>= 1) S += __shfl_xor_sync(0xffffffffu, S, o);
        float lse = logf(S);
        float lp0 = (la0 - m) - lse;
        float lp1 = (la1 - m) - lse;
        float pt = expf(lp0) * lp0 + expf(lp1) * lp1;
#pragma unroll
        for (int o = 16; o; o >>= 1) pt += __shfl_xor_sync(0xffffffffu, pt, o);
        int idx = (int)out[(size_t)b * NL + t];
        float lpA = __shfl_sync(0xffffffffu, lp0, idx >> 1);
        float lpB = __shfl_sync(0xffffffffu, lp1, idx >> 1);
        float lp = (idx & 1) ? lpB : lpA;
        slp += lp;
        plp += pt;
        ep *= expf(lp);
    }
    if (lane == 0) {
        out[NB*NL + b]        = slp;
        out[NB*NL + NB + b]   = plp;
        out[NB*NL + 2*NB + b] = ep;
    }
}

// ---------------- launcher ----------------
extern "C" void kernel_launch(void* const* d_in, const int* in_sizes, int n_in,
                              void* d_out, int out_size)
{
    const float* attr = (const float*)d_in[0];
    const float* W_a  = (const float*)d_in[1];
    const float* b_a  = (const float*)d_in[2];
    const float* W_ih = (const float*)d_in[3];
    const float* W_hh = (const float*)d_in[4];
    const float* b_ih = (const float*)d_in[5];
    const float* b_hh = (const float*)d_in[6];
    const float* W_v  = (const float*)d_in[7];
    const float* b_v  = (const float*)d_in[8];
    float* out = (float*)d_out;

    Keys keys;
    for (int t = 0; t < NL; t++) {
        uint32_t s0, s1;
        threefry2x32(0u, 42u, 0u, (uint32_t)t, s0, s1);
        keys.a[t] = s0; keys.b[t] = s1;
    }

    static int smem_set = 0;
    if (!smem_set) {
        cudaFuncSetAttribute(sender_kernel, cudaFuncAttributeMaxDynamicSharedMemorySize,
                             SMEM_FLOATS * sizeof(float));
        smem_set = 1;
    }

    prep_kernel<<<1024, 256>>>(W_hh, W_ih, W_a, b_ih, b_hh);
    prep_gum<<<(NL*NB*NV + 255) / 256, 256>>>(keys);
    sender_kernel<<<NBLK, NT, SMEM_FLOATS * sizeof(float)>>>(attr, W_v, b_v, b_a, out);
    post_kernel<<<NB / 8, 256>>>(out);
}